// round 15
// baseline (speedup 1.0000x reference)
#include <cuda_runtime.h>
#include <cuda_bf16.h>
#include <cuda_fp16.h>
#include <cstdint>
#include <math.h>

#define NB 4
#define NS 2048
#define ND 2048
#define NH 16
#define NHD 128
#define ROWS (NB*NS)        /* 8192 */
#define QKV_COLS (3*ND)     /* 6144 */

// ---------------- scratch (device globals: allocation-free rule) ----------
__device__ __half g_xh[(size_t)ROWS * ND];                 // x single fp16
__device__ __half g_ao[(size_t)ROWS * ND];                 // attn out (single)
__device__ __half g_wqT[(size_t)QKV_COLS * ND];            // Wqkv^T [6144][2048]
__device__ __half g_woT[(size_t)ND * ND];                  // Wout^T [2048][2048]
// per-head QKV: [B*H][S][HD]; Q split hi/lo, K and V single fp16
__device__ __half g_qhh[(size_t)ROWS * ND];
__device__ __half g_qll[(size_t)ROWS * ND];
__device__ __half g_kk[(size_t)ROWS * ND];
__device__ __half g_vv[(size_t)ROWS * ND];

// ---------------- PTX helpers (baseline features only: sm_80+) ------------
__device__ __forceinline__ uint32_t smem_u32(const void* p) {
    uint32_t a;
    asm("{ .reg .u64 t; cvta.to.shared.u64 t, %1; cvt.u32.u64 %0, t; }"
        : "=r"(a) : "l"(p));
    return a;
}

__device__ __forceinline__ void cpa16(uint32_t s, const void* g) {
    asm volatile("cp.async.cg.shared.global [%0], [%1], 16;" :: "r"(s), "l"(g));
}
#define CP_COMMIT() asm volatile("cp.async.commit_group;" ::: "memory")
#define CP_WAIT(n)  asm volatile("cp.async.wait_group %0;" :: "n"(n) : "memory")

__device__ __forceinline__ void ldsm4(uint32_t* r, uint32_t addr) {
    asm volatile("ldmatrix.sync.aligned.m8n8.x4.shared.b16 {%0,%1,%2,%3}, [%4];"
                 : "=r"(r[0]), "=r"(r[1]), "=r"(r[2]), "=r"(r[3]) : "r"(addr));
}
__device__ __forceinline__ void ldsm4t(uint32_t* r, uint32_t addr) {
    asm volatile("ldmatrix.sync.aligned.m8n8.x4.trans.shared.b16 {%0,%1,%2,%3}, [%4];"
                 : "=r"(r[0]), "=r"(r[1]), "=r"(r[2]), "=r"(r[3]) : "r"(addr));
}

// fp16 mma
__device__ __forceinline__ void mma16816h(float* d, const uint32_t* a,
                                          const uint32_t* b) {
    asm volatile(
        "mma.sync.aligned.m16n8k16.row.col.f32.f16.f16.f32 "
        "{%0,%1,%2,%3}, {%4,%5,%6,%7}, {%8,%9}, {%0,%1,%2,%3};"
        : "+f"(d[0]), "+f"(d[1]), "+f"(d[2]), "+f"(d[3])
        : "r"(a[0]), "r"(a[1]), "r"(a[2]), "r"(a[3]), "r"(b[0]), "r"(b[1]));
}

__device__ __forceinline__ float ex2f(float x) {
    float y;
    asm("ex2.approx.f32 %0, %1;" : "=f"(y) : "f"(x));
    return y;
}

#define PACK2(lo16, hi16) (((uint32_t)(hi16) << 16) | (uint32_t)(lo16))
#define HFU(x) __half_as_ushort(x)

__device__ __forceinline__ uint32_t split_pair_h(float a, float b, uint32_t& lo) {
    __half h0 = __float2half_rn(a), h1 = __float2half_rn(b);
    __half e0 = __float2half_rn(a - __half2float(h0));
    __half e1 = __float2half_rn(b - __half2float(h1));
    lo = PACK2(HFU(e0), HFU(e1));
    return PACK2(HFU(h0), HFU(h1));
}
__device__ __forceinline__ uint32_t pack_h(float a, float b) {
    return PACK2(HFU(__float2half_rn(a)), HFU(__float2half_rn(b)));
}

// ---------------------------------------------------------------------------
// conversion kernels
// ---------------------------------------------------------------------------
__global__ void cvt_h(const float4* __restrict__ in, uint2* __restrict__ hi)
{
    int i = blockIdx.x * blockDim.x + threadIdx.x;
    float4 v = in[i];
    uint2 uh;
    uh.x = pack_h(v.x, v.y);
    uh.y = pack_h(v.z, v.w);
    hi[i] = uh;
}

// W [K][N] fp32  ->  T [N][K] single fp16
__global__ void cvt_T_h(const float* __restrict__ W, __half* __restrict__ Th,
                        int K, int N)
{
    __shared__ float tile[32][33];
    int n0 = blockIdx.x * 32, k0 = blockIdx.y * 32;
    int tx = threadIdx.x, ty = threadIdx.y;  // 32 x 8
    #pragma unroll
    for (int r = 0; r < 4; r++)
        tile[ty + r*8][tx] = W[(size_t)(k0 + ty + r*8) * N + n0 + tx];
    __syncthreads();
    #pragma unroll
    for (int r = 0; r < 4; r++) {
        float v = tile[tx][ty + r*8];
        Th[(size_t)(n0 + ty + r*8) * K + k0 + tx] = __float2half_rn(v);
    }
}

// ---------------------------------------------------------------------------
// fp16 1-term GEMM via mma.sync: C = A @ B^T + bias.
// CTA 128x128, BK=64, 8 warps (4m x 2n), warp tile 32x64, 3-stage cp.async,
// 96KB smem -> 2 CTAs/SM. Fragments double-buffered across the four k16
// halves (prefetch ks+1 during ks's mma) to hide ldsm latency.
// EPI=0: fp32 C + bias. EPI=1: per-head QKV (Q split hi/lo, K/V single).
// ---------------------------------------------------------------------------
#define STAGES 3
#define STAGE_BYTES 32768      /* A 16K | B 16K */
#define GEMM_SMEM (STAGES * STAGE_BYTES)   /* 96 KB */
#define SWZ8(row, chunk) ((((chunk) ^ ((row) & 7)) << 4))

__device__ __forceinline__ void issue_stage(
    uint32_t sb_stage, const __half* __restrict__ A,
    const __half* __restrict__ B,
    int rowBase, int colBase, int k0, int K, int t)
{
    #pragma unroll
    for (int u = 0; u < 4; u++) {
        int idx = t + 256*u;               // 0..1023
        int row = idx >> 3, chunk = idx & 7;
        uint32_t soff = (uint32_t)(row*128 + SWZ8(row, chunk));
        size_t ge = k0 + chunk*8;
        cpa16(sb_stage +         soff, A + (size_t)(rowBase + row) * K + ge);
        cpa16(sb_stage + 16384 + soff, B + (size_t)(colBase + row) * K + ge);
    }
    CP_COMMIT();
}

template<int EPI>
__global__ __launch_bounds__(256, 2)
void gemm_mma(const __half* __restrict__ A, const __half* __restrict__ B,
              const float* __restrict__ bias, float* __restrict__ C,
              __half* __restrict__ q_h, __half* __restrict__ q_l,
              __half* __restrict__ k_s, __half* __restrict__ v_s,
              int M, int N, int K)
{
    extern __shared__ char sm[];
    const uint32_t sb = smem_u32(sm);

    const int t = threadIdx.x, lane = t & 31, w = t >> 5;
    const int warp_m = w & 3, warp_n = w >> 2;   // 4 x 2
    const int rowBase = blockIdx.y * 128;
    const int colBase = blockIdx.x * 128;
    const int ksteps  = K >> 6;
    const int mat = lane >> 3, r8 = lane & 7;

    float acc[2][8][4];
    #pragma unroll
    for (int i = 0; i < 2; i++)
        #pragma unroll
        for (int j = 0; j < 8; j++)
            #pragma unroll
            for (int q = 0; q < 4; q++) acc[i][j][q] = 0.f;

    issue_stage(sb,               A, B, rowBase, colBase, 0,  K, t);
    issue_stage(sb + STAGE_BYTES, A, B, rowBase, colBase, 64, K, t);

    int rowA[2], rowB[4];
    #pragma unroll
    for (int fm = 0; fm < 2; fm++)
        rowA[fm] = warp_m*32 + fm*16 + (mat & 1)*8 + r8;
    #pragma unroll
    for (int fb = 0; fb < 4; fb++)
        rowB[fb] = warp_n*64 + fb*16 + (mat >> 1)*8 + r8;

    const int ckAo = mat >> 1, ckBo = mat & 1;

    for (int i = 0; i < ksteps; i++) {
        CP_WAIT(1);
        __syncthreads();
        const uint32_t st = sb + (uint32_t)(i % 3) * STAGE_BYTES;

        // double-buffered fragments: preload ks=0
        uint32_t rhB[2][4][4], rhA[2][2][4];
        #pragma unroll
        for (int fb = 0; fb < 4; fb++)
            ldsm4(rhB[0][fb],
                  st + 16384 + (uint32_t)(rowB[fb]*128 + SWZ8(rowB[fb], ckBo)));
        #pragma unroll
        for (int fm = 0; fm < 2; fm++)
            ldsm4(rhA[0][fm],
                  st + (uint32_t)(rowA[fm]*128 + SWZ8(rowA[fm], ckAo)));

        // refill slot (i+2)%3 == (i-1)%3 (reads done before barrier above);
        // LDGSTS burst overlaps the ldsm latency of the ks=0 preload.
        if (i + 2 < ksteps)
            issue_stage(sb + (uint32_t)((i + 2) % 3) * STAGE_BYTES,
                        A, B, rowBase, colBase, (i + 2)*64, K, t);
        else
            CP_COMMIT();   // keep group accounting uniform

        #pragma unroll
        for (int ks = 0; ks < 4; ks++) {
            const int cur = ks & 1;
            if (ks < 3) {
                const int ckA = (ks+1)*2 + ckAo;
                const int ckB = (ks+1)*2 + ckBo;
                #pragma unroll
                for (int fb = 0; fb < 4; fb++)
                    ldsm4(rhB[cur^1][fb],
                          st + 16384 + (uint32_t)(rowB[fb]*128 +
                                                  SWZ8(rowB[fb], ckB)));
                #pragma unroll
                for (int fm = 0; fm < 2; fm++)
                    ldsm4(rhA[cur^1][fm],
                          st + (uint32_t)(rowA[fm]*128 + SWZ8(rowA[fm], ckA)));
            }
            #pragma unroll
            for (int fm = 0; fm < 2; fm++)
                #pragma unroll
                for (int fb = 0; fb < 4; fb++) {
                    mma16816h(acc[fm][2*fb+0], rhA[cur][fm], rhB[cur][fb]);
                    mma16816h(acc[fm][2*fb+1], rhA[cur][fm], rhB[cur][fb]+2);
                }
        }
    }

    const int qrow = lane >> 2, qcol = (lane & 3) * 2;
    #pragma unroll
    for (int fn = 0; fn < 8; fn++) {
        const int col = colBase + warp_n*64 + fn*8 + qcol;
        const float b0 = bias[col], b1 = bias[col + 1];
        if (EPI == 0) {
            #pragma unroll
            for (int fm = 0; fm < 2; fm++) {
                const int row0 = rowBase + warp_m*32 + fm*16 + qrow;
                float2 v0 = make_float2(acc[fm][fn][0] + b0, acc[fm][fn][1] + b1);
                float2 v1 = make_float2(acc[fm][fn][2] + b0, acc[fm][fn][3] + b1);
                *(float2*)&C[(size_t)row0 * N + col]       = v0;
                *(float2*)&C[(size_t)(row0 + 8) * N + col] = v1;
            }
        } else {
            const int sel = col >> 11, hh = (col >> 7) & 15, hd = col & 127;
            #pragma unroll
            for (int fm = 0; fm < 2; fm++) {
                const int r0 = rowBase + warp_m*32 + fm*16 + qrow;
                #pragma unroll
                for (int rr = 0; rr < 2; rr++) {
                    const int r = r0 + rr*8;
                    float va = acc[fm][fn][rr*2+0] + b0;
                    float vb = acc[fm][fn][rr*2+1] + b1;
                    size_t o = (((size_t)((r >> 11)*NH + hh) * NS +
                                 (r & 2047)) * NHD + hd);
                    if (sel == 0) {
                        uint32_t lo, hi = split_pair_h(va, vb, lo);
                        *(uint32_t*)&q_h[o] = hi;
                        *(uint32_t*)&q_l[o] = lo;
                    } else {
                        __half* d = (sel == 1) ? k_s : v_s;
                        *(uint32_t*)&d[o] = pack_h(va, vb);
                    }
                }
            }
        }
    }
}

// ---------------------------------------------------------------------------
// Flash attention via fp16 mma. Q 2-term (hi/lo); K, V, P single fp16.
// Static-max softmax; heavy tiles first; register-stage pipelining.
// smem: 3 KV stages of 32KB (K 16K | V 16K) + persistent Q 64KB (hi|lo).
// ---------------------------------------------------------------------------
#define KV_STAGE 32768
#define FLASH_SMEM (3*KV_STAGE + 65536)   /* 163840 */
#define SWZF(row, chunk) (((chunk) ^ ((row) & 7)) << 4)

__device__ __forceinline__ void flash_load_kv(
    uint32_t st, const __half* __restrict__ k_s,
    const __half* __restrict__ v_s, size_t hb, int kt, int t)
{
    #pragma unroll
    for (int u = 0; u < 4; u++) {
        int idx = t + 256*u;                 // 0..1023
        int row = idx >> 4, chunk = idx & 15;
        uint32_t soff = (uint32_t)(row*256 + SWZF(row, chunk));
        size_t g = hb + (size_t)(kt*64 + row)*NHD + chunk*8;
        cpa16(st +         soff, k_s + g);
        cpa16(st + 16384 + soff, v_s + g);
    }
    CP_COMMIT();
}

__global__ __launch_bounds__(256, 1)
void flash_mma(const __half* __restrict__ qh, const __half* __restrict__ ql,
               const __half* __restrict__ k_s, const __half* __restrict__ v_s,
               __half* __restrict__ ao)
{
    extern __shared__ char sm[];
    const uint32_t sb = smem_u32(sm);
    const uint32_t qst = sb + 3*KV_STAGE;    // persistent Q region

    const int qt = (NS/128 - 1) - blockIdx.x;   // heavy tiles first
    const int h = blockIdx.y, b = blockIdx.z;
    const int t = threadIdx.x, lane = t & 31, w = t >> 5;
    const size_t hb = (size_t)(b*NH + h) * NS * NHD;

    const float L2E   = 1.4426950408889634f;
    const float scale = 0.08838834764831845f;          // 1/sqrt(128)
    const float slope = exp2f(-0.5f * (float)(h + 1)); // ALiBi, H=16
    const float c1  = scale * L2E;
    const float sl2 = slope * L2E;
    const float mc8 = -8.0f * L2E;
    const int r8 = lane & 7, m01 = (lane >> 3) & 1, m2 = lane >> 4;
    const int qr = lane >> 2, qc = (lane & 3) * 2;
    const int rg0 = qt*128 + w*16 + qr;                // global q row (c0/c1)

    // stage Q (hi|lo) into the persistent region
    #pragma unroll
    for (int u = 0; u < 8; u++) {
        int idx = t + 256*u;                 // 0..2047
        int row = idx >> 4, chunk = idx & 15;
        uint32_t soff = (uint32_t)(row*256 + SWZF(row, chunk));
        size_t g = hb + (size_t)(qt*128 + row)*NHD + chunk*8;
        cpa16(qst +         soff, qh + g);
        cpa16(qst + 32768 + soff, ql + g);
    }
    CP_COMMIT();                             // group: Q
    flash_load_kv(sb,            k_s, v_s, hb, 0, t);   // group: KV0
    flash_load_kv(sb + KV_STAGE, k_s, v_s, hb, 1, t);   // group: KV1

    CP_WAIT(2);                              // Q complete
    __syncthreads();

    // Q fragments -> registers
    uint32_t fqh[8][4], fql[8][4];
    {
        const int qrow = w*16 + m01*8 + r8;
        #pragma unroll
        for (int kc = 0; kc < 8; kc++) {
            uint32_t qa = qst + (uint32_t)(qrow*256 + SWZF(qrow, kc*2 + m2));
            ldsm4(fqh[kc], qa);
            ldsm4(fql[kc], qa + 32768);
        }
    }

    float l0 = 0.f, l1 = 0.f;
    float acc_o[16][4];
    #pragma unroll
    for (int i = 0; i < 16; i++)
        #pragma unroll
        for (int j = 0; j < 4; j++) acc_o[i][j] = 0.f;

    const int nkt = 2*qt + 2;
    for (int kt = 0; kt < nkt; kt++) {
        CP_WAIT(1);
        __syncthreads();
        const uint32_t st = sb + (uint32_t)(kt % 3)*KV_STAGE;

        // ---- S = Q K^T (2-term), K frags double-buffered over ng ----
        float s_[8][4];
        #pragma unroll
        for (int i = 0; i < 8; i++)
            #pragma unroll
            for (int j = 0; j < 4; j++) s_[i][j] = 0.f;

        #pragma unroll
        for (int kc = 0; kc < 8; kc++) {
            const int kchk = kc*2 + m01;
            uint32_t rh[2][4];
            {
                int krow = m2*8 + r8;                // ng = 0
                ldsm4(rh[0], st + (uint32_t)(krow*256 + SWZF(krow, kchk)));
            }
            if (kc == 0) {
                if (kt + 2 < nkt)
                    flash_load_kv(sb + (uint32_t)((kt + 2) % 3)*KV_STAGE,
                                  k_s, v_s, hb, kt + 2, t);
                else
                    CP_COMMIT();
            }
            #pragma unroll
            for (int ng = 0; ng < 4; ng++) {
                const int cur = ng & 1;
                if (ng < 3) {
                    int krow = (ng+1)*16 + m2*8 + r8;
                    ldsm4(rh[cur^1],
                          st + (uint32_t)(krow*256 + SWZF(krow, kchk)));
                }
                mma16816h(s_[ng*2+0], fqh[kc], rh[cur]);
                mma16816h(s_[ng*2+0], fql[kc], rh[cur]);
                mma16816h(s_[ng*2+1], fqh[kc], rh[cur]+2);
                mma16816h(s_[ng*2+1], fql[kc], rh[cur]+2);
            }
        }

        // ---- static-max softmax ----
        const bool diag = (kt >= 2*qt);
        const float baseA = fmaf((float)(kt*64 + qc - rg0), sl2, mc8);
        const float baseB = baseA - 8.0f*sl2;   // rows rg0+8
        if (diag) {
            #pragma unroll
            for (int nt = 0; nt < 8; nt++) {
                #pragma unroll
                for (int jj = 0; jj < 2; jj++) {
                    const float cf = (float)(nt*8 + jj);
                    float a0 = fmaf(s_[nt][jj],     c1, fmaf(cf, sl2, baseA));
                    float a1 = fmaf(s_[nt][2 + jj], c1, fmaf(cf, sl2, baseB));
                    int col = kt*64 + nt*8 + qc + jj;
                    if (col > rg0)     a0 = -10000.f;
                    if (col > rg0 + 8) a1 = -10000.f;
                    float p0 = ex2f(a0), p1 = ex2f(a1);
                    l0 += p0; l1 += p1;
                    s_[nt][jj] = p0; s_[nt][2 + jj] = p1;
                }
            }
        } else {
            #pragma unroll
            for (int nt = 0; nt < 8; nt++) {
                #pragma unroll
                for (int jj = 0; jj < 2; jj++) {
                    const float cf = (float)(nt*8 + jj);
                    float a0 = fmaf(s_[nt][jj],     c1, fmaf(cf, sl2, baseA));
                    float a1 = fmaf(s_[nt][2 + jj], c1, fmaf(cf, sl2, baseB));
                    float p0 = ex2f(a0), p1 = ex2f(a1);
                    l0 += p0; l1 += p1;
                    s_[nt][jj] = p0; s_[nt][2 + jj] = p1;
                }
            }
        }

        // ---- O += P V (P single fp16), V frags double-buffered over ng ----
        #pragma unroll
        for (int kc = 0; kc < 4; kc++) {
            uint32_t ph[4];
            {
                const float* pa = s_[2*kc];
                const float* pb = s_[2*kc + 1];
                ph[0] = pack_h(pa[0], pa[1]);
                ph[1] = pack_h(pa[2], pa[3]);
                ph[2] = pack_h(pb[0], pb[1]);
                ph[3] = pack_h(pb[2], pb[3]);
            }
            const int vrow = kc*16 + m01*8 + r8;
            const uint32_t vbase = st + 16384 + (uint32_t)(vrow*256);
            uint32_t wh[2][4];
            ldsm4t(wh[0], vbase + (uint32_t)SWZF(vrow, m2));   // ng = 0
            #pragma unroll
            for (int ng = 0; ng < 8; ng++) {
                const int cur = ng & 1;
                if (ng < 7)
                    ldsm4t(wh[cur^1],
                           vbase + (uint32_t)SWZF(vrow, (ng+1)*2 + m2));
                mma16816h(acc_o[ng*2+0], ph, wh[cur]);
                mma16816h(acc_o[ng*2+1], ph, wh[cur]+2);
            }
        }
    }

    // ---- finalize ----
    l0 += __shfl_xor_sync(0xffffffffu, l0, 1);
    l0 += __shfl_xor_sync(0xffffffffu, l0, 2);
    l1 += __shfl_xor_sync(0xffffffffu, l1, 1);
    l1 += __shfl_xor_sync(0xffffffffu, l1, 2);
    const float inv0 = 1.f / l0, inv1 = 1.f / l1;

    const size_t row0 = (size_t)(b*NS) + qt*128 + w*16 + qr;
    #pragma unroll
    for (int nt = 0; nt < 16; nt++) {
        int col = h*NHD + nt*8 + qc;
        *(uint32_t*)&ao[row0 * ND + col] =
            pack_h(acc_o[nt][0]*inv0, acc_o[nt][1]*inv0);
        *(uint32_t*)&ao[(row0 + 8) * ND + col] =
            pack_h(acc_o[nt][2]*inv1, acc_o[nt][3]*inv1);
    }
}

// ---------------------------------------------------------------------------
extern "C" void kernel_launch(void* const* d_in, const int* in_sizes, int n_in,
                              void* d_out, int out_size)
{
    const float* x    = (const float*)d_in[0];
    const float* Wqkv = (const float*)d_in[1];
    const float* bqkv = (const float*)d_in[2];
    const float* Wout = (const float*)d_in[3];
    const float* bout = (const float*)d_in[4];
    float* out = (float*)d_out;

    __half *xh, *ao, *wqT, *woT, *qh, *ql, *ks, *vs;
    cudaGetSymbolAddress((void**)&xh,   g_xh);
    cudaGetSymbolAddress((void**)&ao,   g_ao);
    cudaGetSymbolAddress((void**)&wqT,  g_wqT);
    cudaGetSymbolAddress((void**)&woT,  g_woT);
    cudaGetSymbolAddress((void**)&qh,   g_qhh);
    cudaGetSymbolAddress((void**)&ql,   g_qll);
    cudaGetSymbolAddress((void**)&ks,   g_kk);
    cudaGetSymbolAddress((void**)&vs,   g_vv);

    cudaFuncSetAttribute((const void*)gemm_mma<0>,
                         cudaFuncAttributeMaxDynamicSharedMemorySize, GEMM_SMEM);
    cudaFuncSetAttribute((const void*)gemm_mma<1>,
                         cudaFuncAttributeMaxDynamicSharedMemorySize, GEMM_SMEM);
    cudaFuncSetAttribute(flash_mma,
                         cudaFuncAttributeMaxDynamicSharedMemorySize, FLASH_SMEM);

    // operand conversions
    cvt_h<<<(ROWS*(size_t)ND/4 + 255)/256, 256>>>((const float4*)x, (uint2*)xh);
    cvt_T_h<<<dim3(QKV_COLS/32, ND/32), dim3(32, 8)>>>(Wqkv, wqT, ND, QKV_COLS);
    cvt_T_h<<<dim3(ND/32, ND/32), dim3(32, 8)>>>(Wout, woT, ND, ND);

    // qkv = x @ Wqkv + b_qkv, written as per-head q(hi/lo), k, v
    gemm_mma<1><<<dim3(QKV_COLS/128, ROWS/128), 256, GEMM_SMEM>>>(
        xh, wqT, bqkv, nullptr,
        qh, ql, ks, vs, ROWS, QKV_COLS, ND);

    // attention -> writes proj A-operand (single fp16) directly
    flash_mma<<<dim3(NS/128, NH, NB), 256, FLASH_SMEM>>>(
        qh, ql, ks, vs, ao);

    // out = attn @ Wout + b_out
    gemm_mma<0><<<dim3(ND/128, ROWS/128), 256, GEMM_SMEM>>>(
        ao, woT, bout, out,
        nullptr, nullptr, nullptr, nullptr, ROWS, ND, ND);
}

// round 16
// speedup vs baseline: 1.0536x; 1.0536x over previous
#include <cuda_runtime.h>
#include <cuda_bf16.h>
#include <cuda_fp16.h>
#include <cstdint>
#include <math.h>

#define NB 4
#define NS 2048
#define ND 2048
#define NH 16
#define NHD 128
#define ROWS (NB*NS)        /* 8192 */
#define QKV_COLS (3*ND)     /* 6144 */

// ---------------- scratch (device globals: allocation-free rule) ----------
__device__ __half g_xh[(size_t)ROWS * ND];                 // x single fp16
__device__ __half g_ao[(size_t)ROWS * ND];                 // attn out (single)
__device__ __half g_wqT[(size_t)QKV_COLS * ND];            // Wqkv^T [6144][2048]
__device__ __half g_woT[(size_t)ND * ND];                  // Wout^T [2048][2048]
// per-head QKV: [B*H][S][HD]; Q split hi/lo, K and V single fp16
__device__ __half g_qhh[(size_t)ROWS * ND];
__device__ __half g_qll[(size_t)ROWS * ND];
__device__ __half g_kk[(size_t)ROWS * ND];
__device__ __half g_vv[(size_t)ROWS * ND];

// ---------------- PTX helpers (baseline features only: sm_80+) ------------
__device__ __forceinline__ uint32_t smem_u32(const void* p) {
    uint32_t a;
    asm("{ .reg .u64 t; cvta.to.shared.u64 t, %1; cvt.u32.u64 %0, t; }"
        : "=r"(a) : "l"(p));
    return a;
}

__device__ __forceinline__ void cpa16(uint32_t s, const void* g) {
    asm volatile("cp.async.cg.shared.global [%0], [%1], 16;" :: "r"(s), "l"(g));
}
#define CP_COMMIT() asm volatile("cp.async.commit_group;" ::: "memory")
#define CP_WAIT(n)  asm volatile("cp.async.wait_group %0;" :: "n"(n) : "memory")

__device__ __forceinline__ void ldsm4(uint32_t* r, uint32_t addr) {
    asm volatile("ldmatrix.sync.aligned.m8n8.x4.shared.b16 {%0,%1,%2,%3}, [%4];"
                 : "=r"(r[0]), "=r"(r[1]), "=r"(r[2]), "=r"(r[3]) : "r"(addr));
}
__device__ __forceinline__ void ldsm4t(uint32_t* r, uint32_t addr) {
    asm volatile("ldmatrix.sync.aligned.m8n8.x4.trans.shared.b16 {%0,%1,%2,%3}, [%4];"
                 : "=r"(r[0]), "=r"(r[1]), "=r"(r[2]), "=r"(r[3]) : "r"(addr));
}

// fp16 mma
__device__ __forceinline__ void mma16816h(float* d, const uint32_t* a,
                                          const uint32_t* b) {
    asm volatile(
        "mma.sync.aligned.m16n8k16.row.col.f32.f16.f16.f32 "
        "{%0,%1,%2,%3}, {%4,%5,%6,%7}, {%8,%9}, {%0,%1,%2,%3};"
        : "+f"(d[0]), "+f"(d[1]), "+f"(d[2]), "+f"(d[3])
        : "r"(a[0]), "r"(a[1]), "r"(a[2]), "r"(a[3]), "r"(b[0]), "r"(b[1]));
}

__device__ __forceinline__ float ex2f(float x) {
    float y;
    asm("ex2.approx.f32 %0, %1;" : "=f"(y) : "f"(x));
    return y;
}

#define PACK2(lo16, hi16) (((uint32_t)(hi16) << 16) | (uint32_t)(lo16))
#define HFU(x) __half_as_ushort(x)

__device__ __forceinline__ uint32_t split_pair_h(float a, float b, uint32_t& lo) {
    __half h0 = __float2half_rn(a), h1 = __float2half_rn(b);
    __half e0 = __float2half_rn(a - __half2float(h0));
    __half e1 = __float2half_rn(b - __half2float(h1));
    lo = PACK2(HFU(e0), HFU(e1));
    return PACK2(HFU(h0), HFU(h1));
}
__device__ __forceinline__ uint32_t pack_h(float a, float b) {
    return PACK2(HFU(__float2half_rn(a)), HFU(__float2half_rn(b)));
}

// ---------------------------------------------------------------------------
// conversion kernels
// ---------------------------------------------------------------------------
__global__ void cvt_h(const float4* __restrict__ in, uint2* __restrict__ hi)
{
    int i = blockIdx.x * blockDim.x + threadIdx.x;
    float4 v = in[i];
    uint2 uh;
    uh.x = pack_h(v.x, v.y);
    uh.y = pack_h(v.z, v.w);
    hi[i] = uh;
}

// W [K][N] fp32  ->  T [N][K] single fp16
__global__ void cvt_T_h(const float* __restrict__ W, __half* __restrict__ Th,
                        int K, int N)
{
    __shared__ float tile[32][33];
    int n0 = blockIdx.x * 32, k0 = blockIdx.y * 32;
    int tx = threadIdx.x, ty = threadIdx.y;  // 32 x 8
    #pragma unroll
    for (int r = 0; r < 4; r++)
        tile[ty + r*8][tx] = W[(size_t)(k0 + ty + r*8) * N + n0 + tx];
    __syncthreads();
    #pragma unroll
    for (int r = 0; r < 4; r++) {
        float v = tile[tx][ty + r*8];
        Th[(size_t)(n0 + ty + r*8) * K + k0 + tx] = __float2half_rn(v);
    }
}

// ---------------------------------------------------------------------------
// fp16 1-term GEMM via mma.sync: C = A @ B^T + bias.   (R14 inner loop; N,K
// compile-time constants for folded addressing.)
// CTA 128x128, BK=64, 8 warps (4m x 2n), warp tile 32x64, 3-stage cp.async,
// 96KB smem -> 2 CTAs/SM. 4 straight-line k16 halves per barrier (ptxas
// schedules ldsm/mma overlap; manual reg double-buffering regressed in R15).
// EPI=0: fp32 C + bias. EPI=1: per-head QKV (Q split hi/lo, K/V single).
// ---------------------------------------------------------------------------
#define STAGES 3
#define STAGE_BYTES 32768      /* A 16K | B 16K */
#define GEMM_SMEM (STAGES * STAGE_BYTES)   /* 96 KB */
#define SWZ8(row, chunk) ((((chunk) ^ ((row) & 7)) << 4))

template<int K>
__device__ __forceinline__ void issue_stage(
    uint32_t sb_stage, const __half* __restrict__ A,
    const __half* __restrict__ B,
    int rowBase, int colBase, int k0, int t)
{
    #pragma unroll
    for (int u = 0; u < 4; u++) {
        int idx = t + 256*u;               // 0..1023
        int row = idx >> 3, chunk = idx & 7;
        uint32_t soff = (uint32_t)(row*128 + SWZ8(row, chunk));
        size_t ge = k0 + chunk*8;
        cpa16(sb_stage +         soff, A + (size_t)(rowBase + row) * K + ge);
        cpa16(sb_stage + 16384 + soff, B + (size_t)(colBase + row) * K + ge);
    }
    CP_COMMIT();
}

template<int EPI, int N, int K>
__global__ __launch_bounds__(256, 2)
void gemm_mma(const __half* __restrict__ A, const __half* __restrict__ B,
              const float* __restrict__ bias, float* __restrict__ C,
              __half* __restrict__ q_h, __half* __restrict__ q_l,
              __half* __restrict__ k_s, __half* __restrict__ v_s)
{
    extern __shared__ char sm[];
    const uint32_t sb = smem_u32(sm);

    const int t = threadIdx.x, lane = t & 31, w = t >> 5;
    const int warp_m = w & 3, warp_n = w >> 2;   // 4 x 2
    const int rowBase = blockIdx.y * 128;
    const int colBase = blockIdx.x * 128;
    constexpr int ksteps = K >> 6;
    const int mat = lane >> 3, r8 = lane & 7;

    float acc[2][8][4];
    #pragma unroll
    for (int i = 0; i < 2; i++)
        #pragma unroll
        for (int j = 0; j < 8; j++)
            #pragma unroll
            for (int q = 0; q < 4; q++) acc[i][j][q] = 0.f;

    issue_stage<K>(sb,               A, B, rowBase, colBase, 0,  t);
    issue_stage<K>(sb + STAGE_BYTES, A, B, rowBase, colBase, 64, t);

    int rowA[2], rowB[4];
    #pragma unroll
    for (int fm = 0; fm < 2; fm++)
        rowA[fm] = warp_m*32 + fm*16 + (mat & 1)*8 + r8;
    #pragma unroll
    for (int fb = 0; fb < 4; fb++)
        rowB[fb] = warp_n*64 + fb*16 + (mat >> 1)*8 + r8;

    for (int i = 0; i < ksteps; i++) {
        CP_WAIT(1);
        __syncthreads();
        const uint32_t st = sb + (uint32_t)(i % 3) * STAGE_BYTES;

        // refill slot (i+2)%3 == (i-1)%3: its reads completed before the
        // barrier above (all warps finished iter i-1's compute).
        if (i + 2 < ksteps)
            issue_stage<K>(sb + (uint32_t)((i + 2) % 3) * STAGE_BYTES,
                           A, B, rowBase, colBase, (i + 2)*64, t);
        else
            CP_COMMIT();   // keep group accounting uniform

        #pragma unroll
        for (int ks = 0; ks < 4; ks++) {
            const int ckA = ks*2 + (mat >> 1);   // 16B chunk index for A
            const int ckB = ks*2 + (mat & 1);    // 16B chunk index for B

            uint32_t rh[4][4];
            #pragma unroll
            for (int fb = 0; fb < 4; fb++) {
                uint32_t off = (uint32_t)(rowB[fb]*128 + SWZ8(rowB[fb], ckB));
                ldsm4(rh[fb], st + 16384 + off);
            }
            uint32_t ahc[2][4];
            #pragma unroll
            for (int fm = 0; fm < 2; fm++) {
                uint32_t off = (uint32_t)(rowA[fm]*128 + SWZ8(rowA[fm], ckA));
                ldsm4(ahc[fm], st + off);
            }

            #pragma unroll
            for (int fm = 0; fm < 2; fm++)
                #pragma unroll
                for (int fb = 0; fb < 4; fb++) {
                    mma16816h(acc[fm][2*fb+0], ahc[fm], rh[fb]);
                    mma16816h(acc[fm][2*fb+1], ahc[fm], rh[fb]+2);
                }
        }
    }

    const int qrow = lane >> 2, qcol = (lane & 3) * 2;
    #pragma unroll
    for (int fn = 0; fn < 8; fn++) {
        const int col = colBase + warp_n*64 + fn*8 + qcol;
        const float b0 = bias[col], b1 = bias[col + 1];
        if (EPI == 0) {
            #pragma unroll
            for (int fm = 0; fm < 2; fm++) {
                const int row0 = rowBase + warp_m*32 + fm*16 + qrow;
                float2 v0 = make_float2(acc[fm][fn][0] + b0, acc[fm][fn][1] + b1);
                float2 v1 = make_float2(acc[fm][fn][2] + b0, acc[fm][fn][3] + b1);
                *(float2*)&C[(size_t)row0 * N + col]       = v0;
                *(float2*)&C[(size_t)(row0 + 8) * N + col] = v1;
            }
        } else {
            const int sel = col >> 11, hh = (col >> 7) & 15, hd = col & 127;
            #pragma unroll
            for (int fm = 0; fm < 2; fm++) {
                const int r0 = rowBase + warp_m*32 + fm*16 + qrow;
                #pragma unroll
                for (int rr = 0; rr < 2; rr++) {
                    const int r = r0 + rr*8;
                    float va = acc[fm][fn][rr*2+0] + b0;
                    float vb = acc[fm][fn][rr*2+1] + b1;
                    size_t o = (((size_t)((r >> 11)*NH + hh) * NS +
                                 (r & 2047)) * NHD + hd);
                    if (sel == 0) {
                        uint32_t lo, hi = split_pair_h(va, vb, lo);
                        *(uint32_t*)&q_h[o] = hi;
                        *(uint32_t*)&q_l[o] = lo;
                    } else {
                        __half* d = (sel == 1) ? k_s : v_s;
                        *(uint32_t*)&d[o] = pack_h(va, vb);
                    }
                }
            }
        }
    }
}

// ---------------------------------------------------------------------------
// Flash attention via fp16 mma. Q 2-term (hi/lo); K, V, P single fp16.
// Static-max softmax; heavy tiles first; register-stage pipelining.
// smem: 3 KV stages of 32KB (K 16K | V 16K) + persistent Q 64KB (hi|lo).
// ---------------------------------------------------------------------------
#define KV_STAGE 32768
#define FLASH_SMEM (3*KV_STAGE + 65536)   /* 163840 */
#define SWZF(row, chunk) (((chunk) ^ ((row) & 7)) << 4)

__device__ __forceinline__ void flash_load_kv(
    uint32_t st, const __half* __restrict__ k_s,
    const __half* __restrict__ v_s, size_t hb, int kt, int t)
{
    #pragma unroll
    for (int u = 0; u < 4; u++) {
        int idx = t + 256*u;                 // 0..1023
        int row = idx >> 4, chunk = idx & 15;
        uint32_t soff = (uint32_t)(row*256 + SWZF(row, chunk));
        size_t g = hb + (size_t)(kt*64 + row)*NHD + chunk*8;
        cpa16(st +         soff, k_s + g);
        cpa16(st + 16384 + soff, v_s + g);
    }
    CP_COMMIT();
}

__global__ __launch_bounds__(256, 1)
void flash_mma(const __half* __restrict__ qh, const __half* __restrict__ ql,
               const __half* __restrict__ k_s, const __half* __restrict__ v_s,
               __half* __restrict__ ao)
{
    extern __shared__ char sm[];
    const uint32_t sb = smem_u32(sm);
    const uint32_t qst = sb + 3*KV_STAGE;    // persistent Q region

    const int qt = (NS/128 - 1) - blockIdx.x;   // heavy tiles first
    const int h = blockIdx.y, b = blockIdx.z;
    const int t = threadIdx.x, lane = t & 31, w = t >> 5;
    const size_t hb = (size_t)(b*NH + h) * NS * NHD;

    const float L2E   = 1.4426950408889634f;
    const float scale = 0.08838834764831845f;          // 1/sqrt(128)
    const float slope = exp2f(-0.5f * (float)(h + 1)); // ALiBi, H=16
    const float c1  = scale * L2E;
    const float sl2 = slope * L2E;
    const float mc8 = -8.0f * L2E;
    const int r8 = lane & 7, m01 = (lane >> 3) & 1, m2 = lane >> 4;
    const int qr = lane >> 2, qc = (lane & 3) * 2;
    const int rg0 = qt*128 + w*16 + qr;                // global q row (c0/c1)

    // stage Q (hi|lo) into the persistent region
    #pragma unroll
    for (int u = 0; u < 8; u++) {
        int idx = t + 256*u;                 // 0..2047
        int row = idx >> 4, chunk = idx & 15;
        uint32_t soff = (uint32_t)(row*256 + SWZF(row, chunk));
        size_t g = hb + (size_t)(qt*128 + row)*NHD + chunk*8;
        cpa16(qst +         soff, qh + g);
        cpa16(qst + 32768 + soff, ql + g);
    }
    CP_COMMIT();                             // group: Q
    flash_load_kv(sb,            k_s, v_s, hb, 0, t);   // group: KV0
    flash_load_kv(sb + KV_STAGE, k_s, v_s, hb, 1, t);   // group: KV1

    CP_WAIT(2);                              // Q complete
    __syncthreads();

    // Q fragments -> registers
    uint32_t fqh[8][4], fql[8][4];
    {
        const int qrow = w*16 + m01*8 + r8;
        #pragma unroll
        for (int kc = 0; kc < 8; kc++) {
            uint32_t qa = qst + (uint32_t)(qrow*256 + SWZF(qrow, kc*2 + m2));
            ldsm4(fqh[kc], qa);
            ldsm4(fql[kc], qa + 32768);
        }
    }

    float l0 = 0.f, l1 = 0.f;
    float acc_o[16][4];
    #pragma unroll
    for (int i = 0; i < 16; i++)
        #pragma unroll
        for (int j = 0; j < 4; j++) acc_o[i][j] = 0.f;

    const int nkt = 2*qt + 2;
    for (int kt = 0; kt < nkt; kt++) {
        CP_WAIT(1);
        __syncthreads();
        const uint32_t st = sb + (uint32_t)(kt % 3)*KV_STAGE;

        // ---- S = Q K^T (2-term), K frags double-buffered over ng ----
        float s_[8][4];
        #pragma unroll
        for (int i = 0; i < 8; i++)
            #pragma unroll
            for (int j = 0; j < 4; j++) s_[i][j] = 0.f;

        #pragma unroll
        for (int kc = 0; kc < 8; kc++) {
            const int kchk = kc*2 + m01;
            uint32_t rh[2][4];
            {
                int krow = m2*8 + r8;                // ng = 0
                ldsm4(rh[0], st + (uint32_t)(krow*256 + SWZF(krow, kchk)));
            }
            if (kc == 0) {
                if (kt + 2 < nkt)
                    flash_load_kv(sb + (uint32_t)((kt + 2) % 3)*KV_STAGE,
                                  k_s, v_s, hb, kt + 2, t);
                else
                    CP_COMMIT();
            }
            #pragma unroll
            for (int ng = 0; ng < 4; ng++) {
                const int cur = ng & 1;
                if (ng < 3) {
                    int krow = (ng+1)*16 + m2*8 + r8;
                    ldsm4(rh[cur^1],
                          st + (uint32_t)(krow*256 + SWZF(krow, kchk)));
                }
                mma16816h(s_[ng*2+0], fqh[kc], rh[cur]);
                mma16816h(s_[ng*2+0], fql[kc], rh[cur]);
                mma16816h(s_[ng*2+1], fqh[kc], rh[cur]+2);
                mma16816h(s_[ng*2+1], fql[kc], rh[cur]+2);
            }
        }

        // ---- static-max softmax ----
        const bool diag = (kt >= 2*qt);
        const float baseA = fmaf((float)(kt*64 + qc - rg0), sl2, mc8);
        const float baseB = baseA - 8.0f*sl2;   // rows rg0+8
        if (diag) {
            #pragma unroll
            for (int nt = 0; nt < 8; nt++) {
                #pragma unroll
                for (int jj = 0; jj < 2; jj++) {
                    const float cf = (float)(nt*8 + jj);
                    float a0 = fmaf(s_[nt][jj],     c1, fmaf(cf, sl2, baseA));
                    float a1 = fmaf(s_[nt][2 + jj], c1, fmaf(cf, sl2, baseB));
                    int col = kt*64 + nt*8 + qc + jj;
                    if (col > rg0)     a0 = -10000.f;
                    if (col > rg0 + 8) a1 = -10000.f;
                    float p0 = ex2f(a0), p1 = ex2f(a1);
                    l0 += p0; l1 += p1;
                    s_[nt][jj] = p0; s_[nt][2 + jj] = p1;
                }
            }
        } else {
            #pragma unroll
            for (int nt = 0; nt < 8; nt++) {
                #pragma unroll
                for (int jj = 0; jj < 2; jj++) {
                    const float cf = (float)(nt*8 + jj);
                    float a0 = fmaf(s_[nt][jj],     c1, fmaf(cf, sl2, baseA));
                    float a1 = fmaf(s_[nt][2 + jj], c1, fmaf(cf, sl2, baseB));
                    float p0 = ex2f(a0), p1 = ex2f(a1);
                    l0 += p0; l1 += p1;
                    s_[nt][jj] = p0; s_[nt][2 + jj] = p1;
                }
            }
        }

        // ---- O += P V (P single fp16), V frags double-buffered over ng ----
        #pragma unroll
        for (int kc = 0; kc < 4; kc++) {
            uint32_t ph[4];
            {
                const float* pa = s_[2*kc];
                const float* pb = s_[2*kc + 1];
                ph[0] = pack_h(pa[0], pa[1]);
                ph[1] = pack_h(pa[2], pa[3]);
                ph[2] = pack_h(pb[0], pb[1]);
                ph[3] = pack_h(pb[2], pb[3]);
            }
            const int vrow = kc*16 + m01*8 + r8;
            const uint32_t vbase = st + 16384 + (uint32_t)(vrow*256);
            uint32_t wh[2][4];
            ldsm4t(wh[0], vbase + (uint32_t)SWZF(vrow, m2));   // ng = 0
            #pragma unroll
            for (int ng = 0; ng < 8; ng++) {
                const int cur = ng & 1;
                if (ng < 7)
                    ldsm4t(wh[cur^1],
                           vbase + (uint32_t)SWZF(vrow, (ng+1)*2 + m2));
                mma16816h(acc_o[ng*2+0], ph, wh[cur]);
                mma16816h(acc_o[ng*2+1], ph, wh[cur]+2);
            }
        }
    }

    // ---- finalize ----
    l0 += __shfl_xor_sync(0xffffffffu, l0, 1);
    l0 += __shfl_xor_sync(0xffffffffu, l0, 2);
    l1 += __shfl_xor_sync(0xffffffffu, l1, 1);
    l1 += __shfl_xor_sync(0xffffffffu, l1, 2);
    const float inv0 = 1.f / l0, inv1 = 1.f / l1;

    const size_t row0 = (size_t)(b*NS) + qt*128 + w*16 + qr;
    #pragma unroll
    for (int nt = 0; nt < 16; nt++) {
        int col = h*NHD + nt*8 + qc;
        *(uint32_t*)&ao[row0 * ND + col] =
            pack_h(acc_o[nt][0]*inv0, acc_o[nt][1]*inv0);
        *(uint32_t*)&ao[(row0 + 8) * ND + col] =
            pack_h(acc_o[nt][2]*inv1, acc_o[nt][3]*inv1);
    }
}

// ---------------------------------------------------------------------------
extern "C" void kernel_launch(void* const* d_in, const int* in_sizes, int n_in,
                              void* d_out, int out_size)
{
    const float* x    = (const float*)d_in[0];
    const float* Wqkv = (const float*)d_in[1];
    const float* bqkv = (const float*)d_in[2];
    const float* Wout = (const float*)d_in[3];
    const float* bout = (const float*)d_in[4];
    float* out = (float*)d_out;

    __half *xh, *ao, *wqT, *woT, *qh, *ql, *ks, *vs;
    cudaGetSymbolAddress((void**)&xh,   g_xh);
    cudaGetSymbolAddress((void**)&ao,   g_ao);
    cudaGetSymbolAddress((void**)&wqT,  g_wqT);
    cudaGetSymbolAddress((void**)&woT,  g_woT);
    cudaGetSymbolAddress((void**)&qh,   g_qhh);
    cudaGetSymbolAddress((void**)&ql,   g_qll);
    cudaGetSymbolAddress((void**)&ks,   g_kk);
    cudaGetSymbolAddress((void**)&vs,   g_vv);

    cudaFuncSetAttribute((const void*)gemm_mma<0, ND, ND>,
                         cudaFuncAttributeMaxDynamicSharedMemorySize, GEMM_SMEM);
    cudaFuncSetAttribute((const void*)gemm_mma<1, QKV_COLS, ND>,
                         cudaFuncAttributeMaxDynamicSharedMemorySize, GEMM_SMEM);
    cudaFuncSetAttribute(flash_mma,
                         cudaFuncAttributeMaxDynamicSharedMemorySize, FLASH_SMEM);

    // operand conversions
    cvt_h<<<(ROWS*(size_t)ND/4 + 255)/256, 256>>>((const float4*)x, (uint2*)xh);
    cvt_T_h<<<dim3(QKV_COLS/32, ND/32), dim3(32, 8)>>>(Wqkv, wqT, ND, QKV_COLS);
    cvt_T_h<<<dim3(ND/32, ND/32), dim3(32, 8)>>>(Wout, woT, ND, ND);

    // qkv = x @ Wqkv + b_qkv, written as per-head q(hi/lo), k, v
    gemm_mma<1, QKV_COLS, ND><<<dim3(QKV_COLS/128, ROWS/128), 256, GEMM_SMEM>>>(
        xh, wqT, bqkv, nullptr, qh, ql, ks, vs);

    // attention -> writes proj A-operand (single fp16) directly
    flash_mma<<<dim3(NS/128, NH, NB), 256, FLASH_SMEM>>>(
        qh, ql, ks, vs, ao);

    // out = attn @ Wout + b_out
    gemm_mma<0, ND, ND><<<dim3(ND/128, ROWS/128), 256, GEMM_SMEM>>>(
        ao, woT, bout, out, nullptr, nullptr, nullptr, nullptr);
}

// round 17
// speedup vs baseline: 1.1273x; 1.0700x over previous
#include <cuda_runtime.h>
#include <cuda_bf16.h>
#include <cuda_fp16.h>
#include <cstdint>
#include <math.h>

#define NB 4
#define NS 2048
#define ND 2048
#define NH 16
#define NHD 128
#define ROWS (NB*NS)        /* 8192 */
#define QKV_COLS (3*ND)     /* 6144 */

// ---------------- scratch (device globals: allocation-free rule) ----------
__device__ __half g_xh[(size_t)ROWS * ND];                 // x single fp16
__device__ __half g_ao[(size_t)ROWS * ND];                 // attn out (single)
__device__ __half g_wqT[(size_t)QKV_COLS * ND];            // Wqkv^T [6144][2048]
__device__ __half g_woT[(size_t)ND * ND];                  // Wout^T [2048][2048]
// per-head QKV: [B*H][S][HD]; all single fp16
__device__ __half g_qq[(size_t)ROWS * ND];
__device__ __half g_kk[(size_t)ROWS * ND];
__device__ __half g_vv[(size_t)ROWS * ND];

// ---------------- PTX helpers (baseline features only: sm_80+) ------------
__device__ __forceinline__ uint32_t smem_u32(const void* p) {
    uint32_t a;
    asm("{ .reg .u64 t; cvta.to.shared.u64 t, %1; cvt.u32.u64 %0, t; }"
        : "=r"(a) : "l"(p));
    return a;
}

__device__ __forceinline__ void cpa16(uint32_t s, const void* g) {
    asm volatile("cp.async.cg.shared.global [%0], [%1], 16;" :: "r"(s), "l"(g));
}
#define CP_COMMIT() asm volatile("cp.async.commit_group;" ::: "memory")
#define CP_WAIT(n)  asm volatile("cp.async.wait_group %0;" :: "n"(n) : "memory")

__device__ __forceinline__ void ldsm4(uint32_t* r, uint32_t addr) {
    asm volatile("ldmatrix.sync.aligned.m8n8.x4.shared.b16 {%0,%1,%2,%3}, [%4];"
                 : "=r"(r[0]), "=r"(r[1]), "=r"(r[2]), "=r"(r[3]) : "r"(addr));
}
__device__ __forceinline__ void ldsm4t(uint32_t* r, uint32_t addr) {
    asm volatile("ldmatrix.sync.aligned.m8n8.x4.trans.shared.b16 {%0,%1,%2,%3}, [%4];"
                 : "=r"(r[0]), "=r"(r[1]), "=r"(r[2]), "=r"(r[3]) : "r"(addr));
}

// fp16 mma
__device__ __forceinline__ void mma16816h(float* d, const uint32_t* a,
                                          const uint32_t* b) {
    asm volatile(
        "mma.sync.aligned.m16n8k16.row.col.f32.f16.f16.f32 "
        "{%0,%1,%2,%3}, {%4,%5,%6,%7}, {%8,%9}, {%0,%1,%2,%3};"
        : "+f"(d[0]), "+f"(d[1]), "+f"(d[2]), "+f"(d[3])
        : "r"(a[0]), "r"(a[1]), "r"(a[2]), "r"(a[3]), "r"(b[0]), "r"(b[1]));
}

__device__ __forceinline__ float ex2f(float x) {
    float y;
    asm("ex2.approx.f32 %0, %1;" : "=f"(y) : "f"(x));
    return y;
}

#define PACK2(lo16, hi16) (((uint32_t)(hi16) << 16) | (uint32_t)(lo16))
#define HFU(x) __half_as_ushort(x)

__device__ __forceinline__ uint32_t pack_h(float a, float b) {
    return PACK2(HFU(__float2half_rn(a)), HFU(__float2half_rn(b)));
}

// ---------------------------------------------------------------------------
// conversion kernels
// ---------------------------------------------------------------------------
__global__ void cvt_h(const float4* __restrict__ in, uint2* __restrict__ hi)
{
    int i = blockIdx.x * blockDim.x + threadIdx.x;
    float4 v = in[i];
    uint2 uh;
    uh.x = pack_h(v.x, v.y);
    uh.y = pack_h(v.z, v.w);
    hi[i] = uh;
}

// W [K][N] fp32  ->  T [N][K] single fp16
__global__ void cvt_T_h(const float* __restrict__ W, __half* __restrict__ Th,
                        int K, int N)
{
    __shared__ float tile[32][33];
    int n0 = blockIdx.x * 32, k0 = blockIdx.y * 32;
    int tx = threadIdx.x, ty = threadIdx.y;  // 32 x 8
    #pragma unroll
    for (int r = 0; r < 4; r++)
        tile[ty + r*8][tx] = W[(size_t)(k0 + ty + r*8) * N + n0 + tx];
    __syncthreads();
    #pragma unroll
    for (int r = 0; r < 4; r++) {
        float v = tile[tx][ty + r*8];
        Th[(size_t)(n0 + ty + r*8) * K + k0 + tx] = __float2half_rn(v);
    }
}

// ---------------------------------------------------------------------------
// fp16 1-term GEMM via mma.sync: C = A @ B^T + bias.  (R16 structure.)
// CTA 128x128, BK=64, 8 warps (4m x 2n), warp tile 32x64, 3-stage cp.async,
// 96KB smem -> 2 CTAs/SM. EPI=0: fp32 C + bias. EPI=1: per-head QKV (all
// single fp16).
// ---------------------------------------------------------------------------
#define STAGES 3
#define STAGE_BYTES 32768      /* A 16K | B 16K */
#define GEMM_SMEM (STAGES * STAGE_BYTES)   /* 96 KB */
#define SWZ8(row, chunk) ((((chunk) ^ ((row) & 7)) << 4))

template<int K>
__device__ __forceinline__ void issue_stage(
    uint32_t sb_stage, const __half* __restrict__ A,
    const __half* __restrict__ B,
    int rowBase, int colBase, int k0, int t)
{
    #pragma unroll
    for (int u = 0; u < 4; u++) {
        int idx = t + 256*u;               // 0..1023
        int row = idx >> 3, chunk = idx & 7;
        uint32_t soff = (uint32_t)(row*128 + SWZ8(row, chunk));
        size_t ge = k0 + chunk*8;
        cpa16(sb_stage +         soff, A + (size_t)(rowBase + row) * K + ge);
        cpa16(sb_stage + 16384 + soff, B + (size_t)(colBase + row) * K + ge);
    }
    CP_COMMIT();
}

template<int EPI, int N, int K>
__global__ __launch_bounds__(256, 2)
void gemm_mma(const __half* __restrict__ A, const __half* __restrict__ B,
              const float* __restrict__ bias, float* __restrict__ C,
              __half* __restrict__ q_s, __half* __restrict__ k_s,
              __half* __restrict__ v_s)
{
    extern __shared__ char sm[];
    const uint32_t sb = smem_u32(sm);

    const int t = threadIdx.x, lane = t & 31, w = t >> 5;
    const int warp_m = w & 3, warp_n = w >> 2;   // 4 x 2
    const int rowBase = blockIdx.y * 128;
    const int colBase = blockIdx.x * 128;
    constexpr int ksteps = K >> 6;
    const int mat = lane >> 3, r8 = lane & 7;

    float acc[2][8][4];
    #pragma unroll
    for (int i = 0; i < 2; i++)
        #pragma unroll
        for (int j = 0; j < 8; j++)
            #pragma unroll
            for (int q = 0; q < 4; q++) acc[i][j][q] = 0.f;

    issue_stage<K>(sb,               A, B, rowBase, colBase, 0,  t);
    issue_stage<K>(sb + STAGE_BYTES, A, B, rowBase, colBase, 64, t);

    int rowA[2], rowB[4];
    #pragma unroll
    for (int fm = 0; fm < 2; fm++)
        rowA[fm] = warp_m*32 + fm*16 + (mat & 1)*8 + r8;
    #pragma unroll
    for (int fb = 0; fb < 4; fb++)
        rowB[fb] = warp_n*64 + fb*16 + (mat >> 1)*8 + r8;

    for (int i = 0; i < ksteps; i++) {
        CP_WAIT(1);
        __syncthreads();
        const uint32_t st = sb + (uint32_t)(i % 3) * STAGE_BYTES;

        // refill slot (i+2)%3 == (i-1)%3: its reads completed before the
        // barrier above (all warps finished iter i-1's compute).
        if (i + 2 < ksteps)
            issue_stage<K>(sb + (uint32_t)((i + 2) % 3) * STAGE_BYTES,
                           A, B, rowBase, colBase, (i + 2)*64, t);
        else
            CP_COMMIT();   // keep group accounting uniform

        #pragma unroll
        for (int ks = 0; ks < 4; ks++) {
            const int ckA = ks*2 + (mat >> 1);   // 16B chunk index for A
            const int ckB = ks*2 + (mat & 1);    // 16B chunk index for B

            uint32_t rh[4][4];
            #pragma unroll
            for (int fb = 0; fb < 4; fb++) {
                uint32_t off = (uint32_t)(rowB[fb]*128 + SWZ8(rowB[fb], ckB));
                ldsm4(rh[fb], st + 16384 + off);
            }
            uint32_t ahc[2][4];
            #pragma unroll
            for (int fm = 0; fm < 2; fm++) {
                uint32_t off = (uint32_t)(rowA[fm]*128 + SWZ8(rowA[fm], ckA));
                ldsm4(ahc[fm], st + off);
            }

            #pragma unroll
            for (int fm = 0; fm < 2; fm++)
                #pragma unroll
                for (int fb = 0; fb < 4; fb++) {
                    mma16816h(acc[fm][2*fb+0], ahc[fm], rh[fb]);
                    mma16816h(acc[fm][2*fb+1], ahc[fm], rh[fb]+2);
                }
        }
    }

    const int qrow = lane >> 2, qcol = (lane & 3) * 2;
    #pragma unroll
    for (int fn = 0; fn < 8; fn++) {
        const int col = colBase + warp_n*64 + fn*8 + qcol;
        const float b0 = bias[col], b1 = bias[col + 1];
        if (EPI == 0) {
            #pragma unroll
            for (int fm = 0; fm < 2; fm++) {
                const int row0 = rowBase + warp_m*32 + fm*16 + qrow;
                float2 v0 = make_float2(acc[fm][fn][0] + b0, acc[fm][fn][1] + b1);
                float2 v1 = make_float2(acc[fm][fn][2] + b0, acc[fm][fn][3] + b1);
                *(float2*)&C[(size_t)row0 * N + col]       = v0;
                *(float2*)&C[(size_t)(row0 + 8) * N + col] = v1;
            }
        } else {
            const int sel = col >> 11, hh = (col >> 7) & 15, hd = col & 127;
            __half* d = (sel == 0) ? q_s : (sel == 1) ? k_s : v_s;
            #pragma unroll
            for (int fm = 0; fm < 2; fm++) {
                const int r0 = rowBase + warp_m*32 + fm*16 + qrow;
                #pragma unroll
                for (int rr = 0; rr < 2; rr++) {
                    const int r = r0 + rr*8;
                    float va = acc[fm][fn][rr*2+0] + b0;
                    float vb = acc[fm][fn][rr*2+1] + b1;
                    size_t o = (((size_t)((r >> 11)*NH + hh) * NS +
                                 (r & 2047)) * NHD + hd);
                    *(uint32_t*)&d[o] = pack_h(va, vb);
                }
            }
        }
    }
}

// ---------------------------------------------------------------------------
// Flash attention via fp16 mma; Q, K, V, P all single fp16.
// Static-max softmax; heavy tiles first; register-stage pipelining.
// smem: 3 KV stages of 32KB (K 16K | V 16K) + persistent Q 32KB.
// ---------------------------------------------------------------------------
#define KV_STAGE 32768
#define FLASH_SMEM (3*KV_STAGE + 32768)   /* 131072 */
#define SWZF(row, chunk) (((chunk) ^ ((row) & 7)) << 4)

__device__ __forceinline__ void flash_load_kv(
    uint32_t st, const __half* __restrict__ k_s,
    const __half* __restrict__ v_s, size_t hb, int kt, int t)
{
    #pragma unroll
    for (int u = 0; u < 4; u++) {
        int idx = t + 256*u;                 // 0..1023
        int row = idx >> 4, chunk = idx & 15;
        uint32_t soff = (uint32_t)(row*256 + SWZF(row, chunk));
        size_t g = hb + (size_t)(kt*64 + row)*NHD + chunk*8;
        cpa16(st +         soff, k_s + g);
        cpa16(st + 16384 + soff, v_s + g);
    }
    CP_COMMIT();
}

__global__ __launch_bounds__(256, 1)
void flash_mma(const __half* __restrict__ q_s, const __half* __restrict__ k_s,
               const __half* __restrict__ v_s, __half* __restrict__ ao)
{
    extern __shared__ char sm[];
    const uint32_t sb = smem_u32(sm);
    const uint32_t qst = sb + 3*KV_STAGE;    // persistent Q region (32KB)

    const int qt = (NS/128 - 1) - blockIdx.x;   // heavy tiles first
    const int h = blockIdx.y, b = blockIdx.z;
    const int t = threadIdx.x, lane = t & 31, w = t >> 5;
    const size_t hb = (size_t)(b*NH + h) * NS * NHD;

    const float L2E   = 1.4426950408889634f;
    const float scale = 0.08838834764831845f;          // 1/sqrt(128)
    const float slope = exp2f(-0.5f * (float)(h + 1)); // ALiBi, H=16
    const float c1  = scale * L2E;
    const float sl2 = slope * L2E;
    const float mc8 = -8.0f * L2E;
    const int r8 = lane & 7, m01 = (lane >> 3) & 1, m2 = lane >> 4;
    const int qr = lane >> 2, qc = (lane & 3) * 2;
    const int rg0 = qt*128 + w*16 + qr;                // global q row (c0/c1)

    // stage Q into the persistent region
    #pragma unroll
    for (int u = 0; u < 8; u++) {
        int idx = t + 256*u;                 // 0..2047
        int row = idx >> 4, chunk = idx & 15;
        uint32_t soff = (uint32_t)(row*256 + SWZF(row, chunk));
        size_t g = hb + (size_t)(qt*128 + row)*NHD + chunk*8;
        cpa16(qst + soff, q_s + g);
    }
    CP_COMMIT();                             // group: Q
    flash_load_kv(sb,            k_s, v_s, hb, 0, t);   // group: KV0
    flash_load_kv(sb + KV_STAGE, k_s, v_s, hb, 1, t);   // group: KV1

    CP_WAIT(2);                              // Q complete
    __syncthreads();

    // Q fragments -> registers
    uint32_t fq[8][4];
    {
        const int qrow = w*16 + m01*8 + r8;
        #pragma unroll
        for (int kc = 0; kc < 8; kc++) {
            uint32_t qa = qst + (uint32_t)(qrow*256 + SWZF(qrow, kc*2 + m2));
            ldsm4(fq[kc], qa);
        }
    }

    float l0 = 0.f, l1 = 0.f;
    float acc_o[16][4];
    #pragma unroll
    for (int i = 0; i < 16; i++)
        #pragma unroll
        for (int j = 0; j < 4; j++) acc_o[i][j] = 0.f;

    const int nkt = 2*qt + 2;
    for (int kt = 0; kt < nkt; kt++) {
        CP_WAIT(1);
        __syncthreads();
        const uint32_t st = sb + (uint32_t)(kt % 3)*KV_STAGE;

        // ---- S = Q K^T (single-term), K frags double-buffered over ng ----
        float s_[8][4];
        #pragma unroll
        for (int i = 0; i < 8; i++)
            #pragma unroll
            for (int j = 0; j < 4; j++) s_[i][j] = 0.f;

        #pragma unroll
        for (int kc = 0; kc < 8; kc++) {
            const int kchk = kc*2 + m01;
            uint32_t rh[2][4];
            {
                int krow = m2*8 + r8;                // ng = 0
                ldsm4(rh[0], st + (uint32_t)(krow*256 + SWZF(krow, kchk)));
            }
            if (kc == 0) {
                if (kt + 2 < nkt)
                    flash_load_kv(sb + (uint32_t)((kt + 2) % 3)*KV_STAGE,
                                  k_s, v_s, hb, kt + 2, t);
                else
                    CP_COMMIT();
            }
            #pragma unroll
            for (int ng = 0; ng < 4; ng++) {
                const int cur = ng & 1;
                if (ng < 3) {
                    int krow = (ng+1)*16 + m2*8 + r8;
                    ldsm4(rh[cur^1],
                          st + (uint32_t)(krow*256 + SWZF(krow, kchk)));
                }
                mma16816h(s_[ng*2+0], fq[kc], rh[cur]);
                mma16816h(s_[ng*2+1], fq[kc], rh[cur]+2);
            }
        }

        // ---- static-max softmax ----
        const bool diag = (kt >= 2*qt);
        const float baseA = fmaf((float)(kt*64 + qc - rg0), sl2, mc8);
        const float baseB = baseA - 8.0f*sl2;   // rows rg0+8
        if (diag) {
            #pragma unroll
            for (int nt = 0; nt < 8; nt++) {
                #pragma unroll
                for (int jj = 0; jj < 2; jj++) {
                    const float cf = (float)(nt*8 + jj);
                    float a0 = fmaf(s_[nt][jj],     c1, fmaf(cf, sl2, baseA));
                    float a1 = fmaf(s_[nt][2 + jj], c1, fmaf(cf, sl2, baseB));
                    int col = kt*64 + nt*8 + qc + jj;
                    if (col > rg0)     a0 = -10000.f;
                    if (col > rg0 + 8) a1 = -10000.f;
                    float p0 = ex2f(a0), p1 = ex2f(a1);
                    l0 += p0; l1 += p1;
                    s_[nt][jj] = p0; s_[nt][2 + jj] = p1;
                }
            }
        } else {
            #pragma unroll
            for (int nt = 0; nt < 8; nt++) {
                #pragma unroll
                for (int jj = 0; jj < 2; jj++) {
                    const float cf = (float)(nt*8 + jj);
                    float a0 = fmaf(s_[nt][jj],     c1, fmaf(cf, sl2, baseA));
                    float a1 = fmaf(s_[nt][2 + jj], c1, fmaf(cf, sl2, baseB));
                    float p0 = ex2f(a0), p1 = ex2f(a1);
                    l0 += p0; l1 += p1;
                    s_[nt][jj] = p0; s_[nt][2 + jj] = p1;
                }
            }
        }

        // ---- O += P V (P single fp16), V frags double-buffered over ng ----
        #pragma unroll
        for (int kc = 0; kc < 4; kc++) {
            uint32_t ph[4];
            {
                const float* pa = s_[2*kc];
                const float* pb = s_[2*kc + 1];
                ph[0] = pack_h(pa[0], pa[1]);
                ph[1] = pack_h(pa[2], pa[3]);
                ph[2] = pack_h(pb[0], pb[1]);
                ph[3] = pack_h(pb[2], pb[3]);
            }
            const int vrow = kc*16 + m01*8 + r8;
            const uint32_t vbase = st + 16384 + (uint32_t)(vrow*256);
            uint32_t wh[2][4];
            ldsm4t(wh[0], vbase + (uint32_t)SWZF(vrow, m2));   // ng = 0
            #pragma unroll
            for (int ng = 0; ng < 8; ng++) {
                const int cur = ng & 1;
                if (ng < 7)
                    ldsm4t(wh[cur^1],
                           vbase + (uint32_t)SWZF(vrow, (ng+1)*2 + m2));
                mma16816h(acc_o[ng*2+0], ph, wh[cur]);
                mma16816h(acc_o[ng*2+1], ph, wh[cur]+2);
            }
        }
    }

    // ---- finalize ----
    l0 += __shfl_xor_sync(0xffffffffu, l0, 1);
    l0 += __shfl_xor_sync(0xffffffffu, l0, 2);
    l1 += __shfl_xor_sync(0xffffffffu, l1, 1);
    l1 += __shfl_xor_sync(0xffffffffu, l1, 2);
    const float inv0 = 1.f / l0, inv1 = 1.f / l1;

    const size_t row0 = (size_t)(b*NS) + qt*128 + w*16 + qr;
    #pragma unroll
    for (int nt = 0; nt < 16; nt++) {
        int col = h*NHD + nt*8 + qc;
        *(uint32_t*)&ao[row0 * ND + col] =
            pack_h(acc_o[nt][0]*inv0, acc_o[nt][1]*inv0);
        *(uint32_t*)&ao[(row0 + 8) * ND + col] =
            pack_h(acc_o[nt][2]*inv1, acc_o[nt][3]*inv1);
    }
}

// ---------------------------------------------------------------------------
extern "C" void kernel_launch(void* const* d_in, const int* in_sizes, int n_in,
                              void* d_out, int out_size)
{
    const float* x    = (const float*)d_in[0];
    const float* Wqkv = (const float*)d_in[1];
    const float* bqkv = (const float*)d_in[2];
    const float* Wout = (const float*)d_in[3];
    const float* bout = (const float*)d_in[4];
    float* out = (float*)d_out;

    __half *xh, *ao, *wqT, *woT, *qs, *ks, *vs;
    cudaGetSymbolAddress((void**)&xh,   g_xh);
    cudaGetSymbolAddress((void**)&ao,   g_ao);
    cudaGetSymbolAddress((void**)&wqT,  g_wqT);
    cudaGetSymbolAddress((void**)&woT,  g_woT);
    cudaGetSymbolAddress((void**)&qs,   g_qq);
    cudaGetSymbolAddress((void**)&ks,   g_kk);
    cudaGetSymbolAddress((void**)&vs,   g_vv);

    cudaFuncSetAttribute((const void*)gemm_mma<0, ND, ND>,
                         cudaFuncAttributeMaxDynamicSharedMemorySize, GEMM_SMEM);
    cudaFuncSetAttribute((const void*)gemm_mma<1, QKV_COLS, ND>,
                         cudaFuncAttributeMaxDynamicSharedMemorySize, GEMM_SMEM);
    cudaFuncSetAttribute(flash_mma,
                         cudaFuncAttributeMaxDynamicSharedMemorySize, FLASH_SMEM);

    // operand conversions
    cvt_h<<<(ROWS*(size_t)ND/4 + 255)/256, 256>>>((const float4*)x, (uint2*)xh);
    cvt_T_h<<<dim3(QKV_COLS/32, ND/32), dim3(32, 8)>>>(Wqkv, wqT, ND, QKV_COLS);
    cvt_T_h<<<dim3(ND/32, ND/32), dim3(32, 8)>>>(Wout, woT, ND, ND);

    // qkv = x @ Wqkv + b_qkv, written as per-head q, k, v (single fp16)
    gemm_mma<1, QKV_COLS, ND><<<dim3(QKV_COLS/128, ROWS/128), 256, GEMM_SMEM>>>(
        xh, wqT, bqkv, nullptr, qs, ks, vs);

    // attention -> writes proj A-operand (single fp16) directly
    flash_mma<<<dim3(NS/128, NH, NB), 256, FLASH_SMEM>>>(
        qs, ks, vs, ao);

    // out = attn @ Wout + b_out
    gemm_mma<0, ND, ND><<<dim3(ND/128, ROWS/128), 256, GEMM_SMEM>>>(
        ao, woT, bout, out, nullptr, nullptr, nullptr);
}